// round 12
// baseline (speedup 1.0000x reference)
#include <cuda_runtime.h>
#include <math.h>

#define NN 20000     // num nodes
#define EE 256000    // num edges
#define HD 128       // hidden dim
#define HD2 256      // 2*HD
#define BQ 2048      // query pairs
#define LDT 132      // padded smem row (tf32 tiles)
#define LDO 264      // padded smem row for selfloop2 fused output

// ---------------- scratch (device globals; no allocation allowed) ------------
__device__ float    g_x[NN * HD];      // embed[h]
__device__ float    g_agg1[NN * HD];   // layer1 neighbor agg
__device__ float    g_x1[NN * HD];     // layer1 output (post relu)
__device__ float    g_agg2[NN * HD2];  // layer2 neighbor agg
__device__ float    g_z[NN * HD];      // latent z (fp32, for hr gather)
__device__ unsigned g_zt[NN * HD];     // z in tf32 (decoder B operand)
__device__ unsigned g_hrt[BQ * HD];    // hr in tf32 (decoder A operand)

// ---------------- small helpers ----------------------------------------------
__device__ __forceinline__ unsigned f2tf32(float f) {
    unsigned u;
    asm("cvt.rna.tf32.f32 %0, %1;" : "=r"(u) : "f"(f));
    return u;
}

__device__ __forceinline__ void mma_tf32(float* d,
    unsigned a0, unsigned a1, unsigned a2, unsigned a3,
    unsigned b0, unsigned b1)
{
    asm volatile(
        "mma.sync.aligned.m16n8k8.row.col.f32.tf32.tf32.f32 "
        "{%0,%1,%2,%3}, {%4,%5,%6,%7}, {%8,%9}, {%0,%1,%2,%3};\n"
        : "+f"(d[0]), "+f"(d[1]), "+f"(d[2]), "+f"(d[3])
        : "r"(a0), "r"(a1), "r"(a2), "r"(a3), "r"(b0), "r"(b1));
}

__device__ __forceinline__ void cp_async16(void* dst_smem, const void* src) {
    unsigned saddr = (unsigned)__cvta_generic_to_shared(dst_smem);
    asm volatile("cp.async.ca.shared.global [%0], [%1], 16;"
                 :: "r"(saddr), "l"(src));
}

// ---------------- zero agg buffers -------------------------------------------
__global__ void zero_kernel() {
    int i = blockIdx.x * blockDim.x + threadIdx.x;
    const int n1 = NN * HD / 4;
    const int n2 = NN * HD2 / 4;
    float4 zv = make_float4(0.f, 0.f, 0.f, 0.f);
    if (i < n1) ((float4*)g_agg1)[i] = zv;
    if (i < n2) ((float4*)g_agg2)[i] = zv;
}

// ---------------- gather: x = embed[h] ---------------------------------------
__global__ void gather_kernel(const int* __restrict__ h, const float* __restrict__ embed) {
    int i = blockIdx.x * blockDim.x + threadIdx.x;   // over NN*HD
    if (i < NN * HD) {
        int row = i >> 7;
        int col = i & 127;
        g_x[i] = embed[h[row] * HD + col];
    }
}

// ---------------- edge message, layer 1 (blocks 2x2) --------------------------
__global__ __launch_bounds__(128) void edge1_kernel(
    const int* __restrict__ src, const int* __restrict__ dst,
    const int* __restrict__ et, const float* __restrict__ norm,
    const float* __restrict__ W1)
{
    int e = blockIdx.x * 4 + (threadIdx.x >> 5);
    int lane = threadIdx.x & 31;
    if (e >= EE) return;
    int s = src[e], d = dst[e], r = et[e];
    float nm = norm[e];
    float4 xv = *(const float4*)(g_x + s * HD + lane * 4);
    const float* wp = W1 + r * 256 + lane * 8;
    float4 w0 = *(const float4*)(wp);
    float4 w1 = *(const float4*)(wp + 4);
    float m0 = (xv.x * w0.x + xv.y * w0.z) * nm;
    float m1 = (xv.x * w0.y + xv.y * w0.w) * nm;
    float m2 = (xv.z * w1.x + xv.w * w1.z) * nm;
    float m3 = (xv.z * w1.y + xv.w * w1.w) * nm;
    float* out = g_agg1 + d * HD + lane * 4;
    atomicAdd(out + 0, m0);
    atomicAdd(out + 1, m1);
    atomicAdd(out + 2, m2);
    atomicAdd(out + 3, m3);
}

// ---------------- edge message, layer 2 (blocks 2x4) --------------------------
__global__ __launch_bounds__(128) void edge2_kernel(
    const int* __restrict__ src, const int* __restrict__ dst,
    const int* __restrict__ et, const float* __restrict__ norm,
    const float* __restrict__ W2)
{
    int e = blockIdx.x * 4 + (threadIdx.x >> 5);
    int lane = threadIdx.x & 31;
    if (e >= EE) return;
    int s = src[e], d = dst[e], r = et[e];
    float nm = norm[e];
    float4 xv = *(const float4*)(g_x1 + s * HD + lane * 4);
    const float* wp = W2 + r * 512 + lane * 16;
    float4 wa0 = *(const float4*)(wp);
    float4 wa1 = *(const float4*)(wp + 4);
    float4 wb0 = *(const float4*)(wp + 8);
    float4 wb1 = *(const float4*)(wp + 12);
    float* out = g_agg2 + d * HD2 + lane * 8;
    atomicAdd(out + 0, (xv.x * wa0.x + xv.y * wa1.x) * nm);
    atomicAdd(out + 1, (xv.x * wa0.y + xv.y * wa1.y) * nm);
    atomicAdd(out + 2, (xv.x * wa0.z + xv.y * wa1.z) * nm);
    atomicAdd(out + 3, (xv.x * wa0.w + xv.y * wa1.w) * nm);
    atomicAdd(out + 4, (xv.z * wb0.x + xv.w * wb1.x) * nm);
    atomicAdd(out + 5, (xv.z * wb0.y + xv.w * wb1.y) * nm);
    atomicAdd(out + 6, (xv.z * wb0.z + xv.w * wb1.z) * nm);
    atomicAdd(out + 7, (xv.z * wb0.w + xv.w * wb1.w) * nm);
}

// ======== self loop layer 1 via TF32 MMA: x1 = relu(x@lw1 + agg1 + b1) =======
// CTA: 128 rows x 128 cols, K=128. 8 warps 4(M)x2(N), warp tile 32x64.
__global__ __launch_bounds__(256) void selfloop1_mma(
    const float* __restrict__ lw1, const float* __restrict__ b1)
{
    extern __shared__ unsigned smem[];
    unsigned* As = smem;               // [128][LDT]  x tile  [m][k]
    unsigned* Bs = smem + 128 * LDT;   // [128][LDT]  lw1^T   [n][j]
    int r0 = blockIdx.x * 128;
    int t = threadIdx.x;

    #pragma unroll
    for (int jj = 0; jj < 16; jj++) {
        int idx = t + jj * 256;
        int m = idx >> 5;
        int k4 = (idx & 31) << 2;
        int row = r0 + m;
        float4 v = make_float4(0.f, 0.f, 0.f, 0.f);
        if (row < NN) v = *(const float4*)(g_x + row * HD + k4);
        unsigned* p = As + m * LDT + k4;
        p[0] = f2tf32(v.x); p[1] = f2tf32(v.y);
        p[2] = f2tf32(v.z); p[3] = f2tf32(v.w);
    }
    #pragma unroll
    for (int jj = 0; jj < 16; jj++) {
        int idx = t + jj * 256;        // over 4096 float4 of lw1
        int j = idx >> 5;              // input-dim row
        int n4 = (idx & 31) << 2;
        float4 v = *(const float4*)(lw1 + j * HD + n4);
        Bs[(n4 + 0) * LDT + j] = f2tf32(v.x);
        Bs[(n4 + 1) * LDT + j] = f2tf32(v.y);
        Bs[(n4 + 2) * LDT + j] = f2tf32(v.z);
        Bs[(n4 + 3) * LDT + j] = f2tf32(v.w);
    }
    __syncthreads();

    int warp = t >> 5, lane = t & 31;
    int warpM = warp >> 1, warpN = warp & 1;
    int lr = lane >> 2, lc = lane & 3;

    float acc[2][8][4];
    #pragma unroll
    for (int i = 0; i < 2; i++)
        #pragma unroll
        for (int j = 0; j < 8; j++)
            #pragma unroll
            for (int c = 0; c < 4; c++) acc[i][j][c] = 0.f;

    const unsigned* Abase = As + (warpM * 32 + lr) * LDT + lc;
    const unsigned* Bbase = Bs + (warpN * 64 + lr) * LDT + lc;

    #pragma unroll
    for (int kt = 0; kt < 16; kt++) {
        int k0 = kt * 8;
        unsigned a[2][4];
        #pragma unroll
        for (int i = 0; i < 2; i++) {
            const unsigned* ap = Abase + i * 16 * LDT + k0;
            a[i][0] = ap[0]; a[i][1] = ap[8 * LDT];
            a[i][2] = ap[4]; a[i][3] = ap[8 * LDT + 4];
        }
        unsigned b[8][2];
        #pragma unroll
        for (int j = 0; j < 8; j++) {
            const unsigned* bp = Bbase + j * 8 * LDT + k0;
            b[j][0] = bp[0]; b[j][1] = bp[4];
        }
        #pragma unroll
        for (int i = 0; i < 2; i++)
            #pragma unroll
            for (int j = 0; j < 8; j++)
                mma_tf32(acc[i][j], a[i][0], a[i][1], a[i][2], a[i][3],
                         b[j][0], b[j][1]);
    }

    #pragma unroll
    for (int i = 0; i < 2; i++) {
        int mrow = r0 + warpM * 32 + i * 16 + lr;
        #pragma unroll
        for (int j = 0; j < 8; j++) {
            int n = warpN * 64 + j * 8 + 2 * lc;
            float bx = b1[n], by = b1[n + 1];
            if (mrow < NN) {
                float2 ag = *(const float2*)(g_agg1 + mrow * HD + n);
                float2 o;
                o.x = fmaxf(acc[i][j][0] + bx + ag.x, 0.f);
                o.y = fmaxf(acc[i][j][1] + by + ag.y, 0.f);
                *(float2*)(g_x1 + mrow * HD + n) = o;
            }
            if (mrow + 8 < NN) {
                float2 ag = *(const float2*)(g_agg1 + (mrow + 8) * HD + n);
                float2 o;
                o.x = fmaxf(acc[i][j][2] + bx + ag.x, 0.f);
                o.y = fmaxf(acc[i][j][3] + by + ag.y, 0.f);
                *(float2*)(g_x1 + (mrow + 8) * HD + n) = o;
            }
        }
    }
}

// == self loop layer 2 + gaussian via TF32 MMA:
//    pre = x1@lw2 + agg2 + b2;  z = pre[:,:128] + sqrt(softplus(pre[:,128:])+1e-8)*eps
// CTA: 128 rows x 256 cols. 8 warps 2(M)x4(N), warp tile 64x64.
__global__ __launch_bounds__(256) void selfloop2_mma(
    const float* __restrict__ lw2, const float* __restrict__ b2,
    const float* __restrict__ eps)
{
    extern __shared__ unsigned smem[];
    unsigned* As = smem;               // [128][LDT]
    unsigned* Bs = smem + 128 * LDT;   // [256][LDT]
    float* outs = (float*)smem;        // [128][LDO], reused post-MMA
    int r0 = blockIdx.x * 128;
    int t = threadIdx.x;

    #pragma unroll
    for (int jj = 0; jj < 16; jj++) {
        int idx = t + jj * 256;
        int m = idx >> 5;
        int k4 = (idx & 31) << 2;
        int row = r0 + m;
        float4 v = make_float4(0.f, 0.f, 0.f, 0.f);
        if (row < NN) v = *(const float4*)(g_x1 + row * HD + k4);
        unsigned* p = As + m * LDT + k4;
        p[0] = f2tf32(v.x); p[1] = f2tf32(v.y);
        p[2] = f2tf32(v.z); p[3] = f2tf32(v.w);
    }
    #pragma unroll
    for (int jj = 0; jj < 32; jj++) {
        int idx = t + jj * 256;        // over 8192 float4 of lw2
        int j = idx >> 6;              // input-dim row (64 float4 per row)
        int n4 = (idx & 63) << 2;
        float4 v = *(const float4*)(lw2 + j * HD2 + n4);
        Bs[(n4 + 0) * LDT + j] = f2tf32(v.x);
        Bs[(n4 + 1) * LDT + j] = f2tf32(v.y);
        Bs[(n4 + 2) * LDT + j] = f2tf32(v.z);
        Bs[(n4 + 3) * LDT + j] = f2tf32(v.w);
    }
    __syncthreads();

    int warp = t >> 5, lane = t & 31;
    int warpM = warp & 1;              // 2 M-groups of 64 rows
    int warpN = warp >> 1;             // 4 N-groups of 64 cols
    int lr = lane >> 2, lc = lane & 3;

    float acc[4][8][4];
    #pragma unroll
    for (int i = 0; i < 4; i++)
        #pragma unroll
        for (int j = 0; j < 8; j++)
            #pragma unroll
            for (int c = 0; c < 4; c++) acc[i][j][c] = 0.f;

    const unsigned* Abase = As + (warpM * 64 + lr) * LDT + lc;
    const unsigned* Bbase = Bs + (warpN * 64 + lr) * LDT + lc;

    #pragma unroll
    for (int kt = 0; kt < 16; kt++) {
        int k0 = kt * 8;
        unsigned a[4][4];
        #pragma unroll
        for (int i = 0; i < 4; i++) {
            const unsigned* ap = Abase + i * 16 * LDT + k0;
            a[i][0] = ap[0]; a[i][1] = ap[8 * LDT];
            a[i][2] = ap[4]; a[i][3] = ap[8 * LDT + 4];
        }
        unsigned b[8][2];
        #pragma unroll
        for (int j = 0; j < 8; j++) {
            const unsigned* bp = Bbase + j * 8 * LDT + k0;
            b[j][0] = bp[0]; b[j][1] = bp[4];
        }
        #pragma unroll
        for (int i = 0; i < 4; i++)
            #pragma unroll
            for (int j = 0; j < 8; j++)
                mma_tf32(acc[i][j], a[i][0], a[i][1], a[i][2], a[i][3],
                         b[j][0], b[j][1]);
    }
    __syncthreads();   // all tile reads done; smem now reusable as outs

    #pragma unroll
    for (int i = 0; i < 4; i++) {
        int rloc = warpM * 64 + i * 16 + lr;
        int grow = r0 + rloc;
        #pragma unroll
        for (int j = 0; j < 8; j++) {
            int n = warpN * 64 + j * 8 + 2 * lc;
            float2 bb = *(const float2*)(b2 + n);
            float2 ag0 = make_float2(0.f, 0.f), ag1 = make_float2(0.f, 0.f);
            if (grow < NN)     ag0 = *(const float2*)(g_agg2 + grow * HD2 + n);
            if (grow + 8 < NN) ag1 = *(const float2*)(g_agg2 + (grow + 8) * HD2 + n);
            outs[rloc * LDO + n]           = acc[i][j][0] + bb.x + ag0.x;
            outs[rloc * LDO + n + 1]       = acc[i][j][1] + bb.y + ag0.y;
            outs[(rloc + 8) * LDO + n]     = acc[i][j][2] + bb.x + ag1.x;
            outs[(rloc + 8) * LDO + n + 1] = acc[i][j][3] + bb.y + ag1.y;
        }
    }
    __syncthreads();

    for (int i = t; i < 128 * HD; i += 256) {
        int r = i >> 7, c = i & 127;
        int row = r0 + r;
        if (row < NN) {
            float mu = outs[r * LDO + c];
            float hv = outs[r * LDO + c + HD];
            float sp = fmaxf(hv, 0.f) + log1pf(expf(-fabsf(hv)));
            float zz = mu + sqrtf(sp + 1e-8f) * eps[row * HD + c];
            g_z[row * HD + c] = zz;
            g_zt[row * HD + c] = f2tf32(zz);
        }
    }
}

// ---------------- hr (tf32) = z[head] * w_rel[rel] ---------------------------
__global__ __launch_bounds__(128) void hr_kernel(
    const int* __restrict__ head_ids, const int* __restrict__ rel_ids,
    const float* __restrict__ w_rel)
{
    int b = blockIdx.x;
    int k = threadIdx.x;
    float v = g_z[head_ids[b] * HD + k] * w_rel[rel_ids[b] * HD + k];
    g_hrt[b * HD + k] = f2tf32(v);
}

// ======== decoder GEMM, B-resident + cp.async double-buffered A ==============
// scores[m][n] = sum_k hr[m][k]*z[n][k].  CTA owns one 128-col n-tile (B
// resident in smem) and streams 8 m-tiles of A (grid.y=2 splits the 16).
__global__ __launch_bounds__(256) void decoder_mma(float* __restrict__ C) {
    extern __shared__ unsigned smem[];
    unsigned* Bs  = smem;                    // [128][LDT] z tile
    unsigned* As0 = smem + 128 * LDT;        // 2 x [128][LDT] A double buffer
    int n0 = blockIdx.x * 128;
    int mbase = blockIdx.y * (BQ / 2);       // 1024-row m-range
    int t = threadIdx.x;

    // stage B tile once (u32, pre-converted; guard 20000 % 128 = 32)
    #pragma unroll
    for (int jj = 0; jj < 16; jj++) {
        int idx = t + jj * 256;
        int n = idx >> 5;
        int k4 = (idx & 31) << 2;
        uint4 v = make_uint4(0u, 0u, 0u, 0u);
        if (n0 + n < NN) v = *(const uint4*)(g_zt + (n0 + n) * HD + k4);
        unsigned* p = Bs + n * LDT + k4;
        p[0] = v.x; p[1] = v.y; p[2] = v.z; p[3] = v.w;
    }
    // prefetch A tile 0
    #pragma unroll
    for (int jj = 0; jj < 16; jj++) {
        int idx = t + jj * 256;
        int m = idx >> 5;
        int k4 = (idx & 31) << 2;
        cp_async16(As0 + m * LDT + k4, g_hrt + (mbase + m) * HD + k4);
    }
    asm volatile("cp.async.commit_group;");

    int warp = t >> 5, lane = t & 31;
    int warpM = warp >> 1, warpN = warp & 1;
    int lr = lane >> 2, lc = lane & 3;

    for (int mt = 0; mt < 8; mt++) {
        unsigned* Acur = As0 + (mt & 1) * (128 * LDT);
        if (mt + 1 < 8) {
            unsigned* Anxt = As0 + ((mt + 1) & 1) * (128 * LDT);
            #pragma unroll
            for (int jj = 0; jj < 16; jj++) {
                int idx = t + jj * 256;
                int m = idx >> 5;
                int k4 = (idx & 31) << 2;
                cp_async16(Anxt + m * LDT + k4,
                           g_hrt + (mbase + (mt + 1) * 128 + m) * HD + k4);
            }
            asm volatile("cp.async.commit_group;");
            asm volatile("cp.async.wait_group 1;");
        } else {
            asm volatile("cp.async.wait_group 0;");
        }
        __syncthreads();

        float acc[2][8][4];
        #pragma unroll
        for (int i = 0; i < 2; i++)
            #pragma unroll
            for (int j = 0; j < 8; j++)
                #pragma unroll
                for (int c = 0; c < 4; c++) acc[i][j][c] = 0.f;

        const unsigned* Abase = Acur + (warpM * 32 + lr) * LDT + lc;
        const unsigned* Bbase = Bs + (warpN * 64 + lr) * LDT + lc;

        #pragma unroll
        for (int kt = 0; kt < 16; kt++) {
            int k0 = kt * 8;
            unsigned a[2][4];
            #pragma unroll
            for (int i = 0; i < 2; i++) {
                const unsigned* ap = Abase + i * 16 * LDT + k0;
                a[i][0] = ap[0]; a[i][1] = ap[8 * LDT];
                a[i][2] = ap[4]; a[i][3] = ap[8 * LDT + 4];
            }
            unsigned b[8][2];
            #pragma unroll
            for (int j = 0; j < 8; j++) {
                const unsigned* bp = Bbase + j * 8 * LDT + k0;
                b[j][0] = bp[0]; b[j][1] = bp[4];
            }
            #pragma unroll
            for (int i = 0; i < 2; i++)
                #pragma unroll
                for (int j = 0; j < 8; j++)
                    mma_tf32(acc[i][j], a[i][0], a[i][1], a[i][2], a[i][3],
                             b[j][0], b[j][1]);
        }

        int m0 = mbase + mt * 128;
        #pragma unroll
        for (int i = 0; i < 2; i++) {
            int mrow = m0 + warpM * 32 + i * 16 + lr;
            #pragma unroll
            for (int j = 0; j < 8; j++) {
                int n = n0 + warpN * 64 + j * 8 + 2 * lc;
                if (n < NN) {
                    float2 v0 = make_float2(acc[i][j][0], acc[i][j][1]);
                    float2 v1 = make_float2(acc[i][j][2], acc[i][j][3]);
                    *(float2*)(C + (long)mrow * NN + n) = v0;
                    *(float2*)(C + (long)(mrow + 8) * NN + n) = v1;
                }
            }
        }
        __syncthreads();   // finish reads of Acur before it is overwritten
    }
}

// ---------------- launch ------------------------------------------------------
extern "C" void kernel_launch(void* const* d_in, const int* in_sizes, int n_in,
                              void* d_out, int out_size) {
    const int*   h        = (const int*)d_in[0];
    const int*   src      = (const int*)d_in[1];
    const int*   dst      = (const int*)d_in[2];
    const int*   etypes   = (const int*)d_in[3];
    const float* norm     = (const float*)d_in[4];
    const int*   head_ids = (const int*)d_in[5];
    const int*   rel_ids  = (const int*)d_in[6];
    const float* embed    = (const float*)d_in[7];
    const float* W1       = (const float*)d_in[8];
    const float* lw1      = (const float*)d_in[9];
    const float* b1       = (const float*)d_in[10];
    const float* W2       = (const float*)d_in[11];
    const float* lw2      = (const float*)d_in[12];
    const float* b2       = (const float*)d_in[13];
    const float* w_rel    = (const float*)d_in[14];
    const float* eps      = (const float*)d_in[15];
    float* out = (float*)d_out;

    static int smem_set = 0;
    int smem_sl1 = 2 * 128 * LDT * sizeof(unsigned);            // 135168
    int smem_sl2 = (128 + 256) * LDT * sizeof(unsigned);        // 202752
    int smem_dec = 3 * 128 * LDT * sizeof(unsigned);            // 202752
    if (!smem_set) {
        cudaFuncSetAttribute(selfloop1_mma,
                             cudaFuncAttributeMaxDynamicSharedMemorySize, smem_sl1);
        cudaFuncSetAttribute(selfloop2_mma,
                             cudaFuncAttributeMaxDynamicSharedMemorySize, smem_sl2);
        cudaFuncSetAttribute(decoder_mma,
                             cudaFuncAttributeMaxDynamicSharedMemorySize, smem_dec);
        smem_set = 1;
    }

    zero_kernel<<<(NN * HD2 / 4 + 255) / 256, 256>>>();
    gather_kernel<<<(NN * HD + 255) / 256, 256>>>(h, embed);
    edge1_kernel<<<EE / 4, 128>>>(src, dst, etypes, norm, W1);
    selfloop1_mma<<<(NN + 127) / 128, 256, smem_sl1>>>(lw1, b1);
    edge2_kernel<<<EE / 4, 128>>>(src, dst, etypes, norm, W2);
    selfloop2_mma<<<(NN + 127) / 128, 256, smem_sl2>>>(lw2, b2, eps);
    hr_kernel<<<BQ, 128>>>(head_ids, rel_ids, w_rel);

    dim3 grid((NN + 127) / 128, 2);   // (157, 2)
    decoder_mma<<<grid, 256, smem_dec>>>(out);
}

// round 13
// speedup vs baseline: 1.6871x; 1.6871x over previous
#include <cuda_runtime.h>
#include <math.h>

#define NN 20000     // num nodes
#define EE 256000    // num edges
#define HD 128       // hidden dim
#define HD2 256      // 2*HD
#define BQ 2048      // query pairs
#define LDT 132      // padded smem row (tf32 tiles)
#define LDO 264      // padded smem row for selfloop2 fused output

// ---------------- scratch (device globals; no allocation allowed) ------------
__device__ float    g_x[NN * HD];      // embed[h]
__device__ float    g_agg1[NN * HD];   // layer1 neighbor agg
__device__ float    g_x1[NN * HD];     // layer1 output (post relu)
__device__ float    g_agg2[NN * HD2];  // layer2 neighbor agg
__device__ float    g_z[NN * HD];      // latent z (fp32, for hr gather)
__device__ unsigned g_zt[NN * HD];     // z in tf32 (decoder B operand)
__device__ unsigned g_hrt[BQ * HD];    // hr in tf32 (decoder A operand)

// ---------------- small helpers ----------------------------------------------
__device__ __forceinline__ unsigned f2tf32(float f) {
    unsigned u;
    asm("cvt.rna.tf32.f32 %0, %1;" : "=r"(u) : "f"(f));
    return u;
}

__device__ __forceinline__ void mma_tf32(float* d,
    unsigned a0, unsigned a1, unsigned a2, unsigned a3,
    unsigned b0, unsigned b1)
{
    asm volatile(
        "mma.sync.aligned.m16n8k8.row.col.f32.tf32.tf32.f32 "
        "{%0,%1,%2,%3}, {%4,%5,%6,%7}, {%8,%9}, {%0,%1,%2,%3};\n"
        : "+f"(d[0]), "+f"(d[1]), "+f"(d[2]), "+f"(d[3])
        : "r"(a0), "r"(a1), "r"(a2), "r"(a3), "r"(b0), "r"(b1));
}

__device__ __forceinline__ void cp_async16(void* dst_smem, const void* src) {
    unsigned saddr = (unsigned)__cvta_generic_to_shared(dst_smem);
    asm volatile("cp.async.ca.shared.global [%0], [%1], 16;"
                 :: "r"(saddr), "l"(src));
}

// cp.async with zero-fill when pred==0 (src not read when src-size is 0)
__device__ __forceinline__ void cp_async16_zfill(void* dst_smem, const void* src, int pred) {
    unsigned saddr = (unsigned)__cvta_generic_to_shared(dst_smem);
    int bytes = pred ? 16 : 0;
    asm volatile("cp.async.ca.shared.global [%0], [%1], 16, %2;"
                 :: "r"(saddr), "l"(src), "r"(bytes));
}

// vector float4 reduction (sm_90+): 1 op instead of 4 scalar atomics
__device__ __forceinline__ void red_add_v4(float* ptr, float a, float b, float c, float d) {
    asm volatile("red.global.add.v4.f32 [%0], {%1, %2, %3, %4};"
                 :: "l"(ptr), "f"(a), "f"(b), "f"(c), "f"(d) : "memory");
}

// ---------------- zero agg buffers -------------------------------------------
__global__ void zero_kernel() {
    int i = blockIdx.x * blockDim.x + threadIdx.x;
    const int n1 = NN * HD / 4;
    const int n2 = NN * HD2 / 4;
    float4 zv = make_float4(0.f, 0.f, 0.f, 0.f);
    if (i < n1) ((float4*)g_agg1)[i] = zv;
    if (i < n2) ((float4*)g_agg2)[i] = zv;
}

// ---------------- gather: x = embed[h] ---------------------------------------
__global__ void gather_kernel(const int* __restrict__ h, const float* __restrict__ embed) {
    int i = blockIdx.x * blockDim.x + threadIdx.x;   // over NN*HD
    if (i < NN * HD) {
        int row = i >> 7;
        int col = i & 127;
        g_x[i] = embed[h[row] * HD + col];
    }
}

// ---------------- edge message, layer 1 (blocks 2x2) --------------------------
__global__ __launch_bounds__(128) void edge1_kernel(
    const int* __restrict__ src, const int* __restrict__ dst,
    const int* __restrict__ et, const float* __restrict__ norm,
    const float* __restrict__ W1)
{
    int e = blockIdx.x * 4 + (threadIdx.x >> 5);
    int lane = threadIdx.x & 31;
    if (e >= EE) return;
    int s = src[e], d = dst[e], r = et[e];
    float nm = norm[e];
    float4 xv = *(const float4*)(g_x + s * HD + lane * 4);
    const float* wp = W1 + r * 256 + lane * 8;
    float4 w0 = *(const float4*)(wp);
    float4 w1 = *(const float4*)(wp + 4);
    float m0 = (xv.x * w0.x + xv.y * w0.z) * nm;
    float m1 = (xv.x * w0.y + xv.y * w0.w) * nm;
    float m2 = (xv.z * w1.x + xv.w * w1.z) * nm;
    float m3 = (xv.z * w1.y + xv.w * w1.w) * nm;
    red_add_v4(g_agg1 + d * HD + lane * 4, m0, m1, m2, m3);
}

// ---------------- edge message, layer 2 (blocks 2x4) --------------------------
__global__ __launch_bounds__(128) void edge2_kernel(
    const int* __restrict__ src, const int* __restrict__ dst,
    const int* __restrict__ et, const float* __restrict__ norm,
    const float* __restrict__ W2)
{
    int e = blockIdx.x * 4 + (threadIdx.x >> 5);
    int lane = threadIdx.x & 31;
    if (e >= EE) return;
    int s = src[e], d = dst[e], r = et[e];
    float nm = norm[e];
    float4 xv = *(const float4*)(g_x1 + s * HD + lane * 4);
    const float* wp = W2 + r * 512 + lane * 16;
    float4 wa0 = *(const float4*)(wp);
    float4 wa1 = *(const float4*)(wp + 4);
    float4 wb0 = *(const float4*)(wp + 8);
    float4 wb1 = *(const float4*)(wp + 12);
    float* out = g_agg2 + d * HD2 + lane * 8;
    red_add_v4(out,
        (xv.x * wa0.x + xv.y * wa1.x) * nm,
        (xv.x * wa0.y + xv.y * wa1.y) * nm,
        (xv.x * wa0.z + xv.y * wa1.z) * nm,
        (xv.x * wa0.w + xv.y * wa1.w) * nm);
    red_add_v4(out + 4,
        (xv.z * wb0.x + xv.w * wb1.x) * nm,
        (xv.z * wb0.y + xv.w * wb1.y) * nm,
        (xv.z * wb0.z + xv.w * wb1.z) * nm,
        (xv.z * wb0.w + xv.w * wb1.w) * nm);
}

// ======== self loop layer 1 via TF32 MMA: x1 = relu(x@lw1 + agg1 + b1) =======
// CTA: 128 rows x 128 cols, K=128. 8 warps 4(M)x2(N), warp tile 32x64.
__global__ __launch_bounds__(256) void selfloop1_mma(
    const float* __restrict__ lw1, const float* __restrict__ b1)
{
    extern __shared__ unsigned smem[];
    unsigned* As = smem;               // [128][LDT]  x tile  [m][k]
    unsigned* Bs = smem + 128 * LDT;   // [128][LDT]  lw1^T   [n][j]
    int r0 = blockIdx.x * 128;
    int t = threadIdx.x;

    #pragma unroll
    for (int jj = 0; jj < 16; jj++) {
        int idx = t + jj * 256;
        int m = idx >> 5;
        int k4 = (idx & 31) << 2;
        int row = r0 + m;
        float4 v = make_float4(0.f, 0.f, 0.f, 0.f);
        if (row < NN) v = *(const float4*)(g_x + row * HD + k4);
        unsigned* p = As + m * LDT + k4;
        p[0] = f2tf32(v.x); p[1] = f2tf32(v.y);
        p[2] = f2tf32(v.z); p[3] = f2tf32(v.w);
    }
    #pragma unroll
    for (int jj = 0; jj < 16; jj++) {
        int idx = t + jj * 256;        // over 4096 float4 of lw1
        int j = idx >> 5;              // input-dim row
        int n4 = (idx & 31) << 2;
        float4 v = *(const float4*)(lw1 + j * HD + n4);
        Bs[(n4 + 0) * LDT + j] = f2tf32(v.x);
        Bs[(n4 + 1) * LDT + j] = f2tf32(v.y);
        Bs[(n4 + 2) * LDT + j] = f2tf32(v.z);
        Bs[(n4 + 3) * LDT + j] = f2tf32(v.w);
    }
    __syncthreads();

    int warp = t >> 5, lane = t & 31;
    int warpM = warp >> 1, warpN = warp & 1;
    int lr = lane >> 2, lc = lane & 3;

    float acc[2][8][4];
    #pragma unroll
    for (int i = 0; i < 2; i++)
        #pragma unroll
        for (int j = 0; j < 8; j++)
            #pragma unroll
            for (int c = 0; c < 4; c++) acc[i][j][c] = 0.f;

    const unsigned* Abase = As + (warpM * 32 + lr) * LDT + lc;
    const unsigned* Bbase = Bs + (warpN * 64 + lr) * LDT + lc;

    #pragma unroll
    for (int kt = 0; kt < 16; kt++) {
        int k0 = kt * 8;
        unsigned a[2][4];
        #pragma unroll
        for (int i = 0; i < 2; i++) {
            const unsigned* ap = Abase + i * 16 * LDT + k0;
            a[i][0] = ap[0]; a[i][1] = ap[8 * LDT];
            a[i][2] = ap[4]; a[i][3] = ap[8 * LDT + 4];
        }
        unsigned b[8][2];
        #pragma unroll
        for (int j = 0; j < 8; j++) {
            const unsigned* bp = Bbase + j * 8 * LDT + k0;
            b[j][0] = bp[0]; b[j][1] = bp[4];
        }
        #pragma unroll
        for (int i = 0; i < 2; i++)
            #pragma unroll
            for (int j = 0; j < 8; j++)
                mma_tf32(acc[i][j], a[i][0], a[i][1], a[i][2], a[i][3],
                         b[j][0], b[j][1]);
    }

    #pragma unroll
    for (int i = 0; i < 2; i++) {
        int mrow = r0 + warpM * 32 + i * 16 + lr;
        #pragma unroll
        for (int j = 0; j < 8; j++) {
            int n = warpN * 64 + j * 8 + 2 * lc;
            float bx = b1[n], by = b1[n + 1];
            if (mrow < NN) {
                float2 ag = *(const float2*)(g_agg1 + mrow * HD + n);
                float2 o;
                o.x = fmaxf(acc[i][j][0] + bx + ag.x, 0.f);
                o.y = fmaxf(acc[i][j][1] + by + ag.y, 0.f);
                *(float2*)(g_x1 + mrow * HD + n) = o;
            }
            if (mrow + 8 < NN) {
                float2 ag = *(const float2*)(g_agg1 + (mrow + 8) * HD + n);
                float2 o;
                o.x = fmaxf(acc[i][j][2] + bx + ag.x, 0.f);
                o.y = fmaxf(acc[i][j][3] + by + ag.y, 0.f);
                *(float2*)(g_x1 + (mrow + 8) * HD + n) = o;
            }
        }
    }
}

// == self loop layer 2 + gaussian via TF32 MMA:
//    pre = x1@lw2 + agg2 + b2;  z = pre[:,:128] + sqrt(softplus(pre[:,128:])+1e-8)*eps
// CTA: 128 rows x 256 cols. 8 warps 2(M)x4(N), warp tile 64x64.
__global__ __launch_bounds__(256) void selfloop2_mma(
    const float* __restrict__ lw2, const float* __restrict__ b2,
    const float* __restrict__ eps)
{
    extern __shared__ unsigned smem[];
    unsigned* As = smem;               // [128][LDT]
    unsigned* Bs = smem + 128 * LDT;   // [256][LDT]
    float* outs = (float*)smem;        // [128][LDO], reused post-MMA
    int r0 = blockIdx.x * 128;
    int t = threadIdx.x;

    #pragma unroll
    for (int jj = 0; jj < 16; jj++) {
        int idx = t + jj * 256;
        int m = idx >> 5;
        int k4 = (idx & 31) << 2;
        int row = r0 + m;
        float4 v = make_float4(0.f, 0.f, 0.f, 0.f);
        if (row < NN) v = *(const float4*)(g_x1 + row * HD + k4);
        unsigned* p = As + m * LDT + k4;
        p[0] = f2tf32(v.x); p[1] = f2tf32(v.y);
        p[2] = f2tf32(v.z); p[3] = f2tf32(v.w);
    }
    #pragma unroll
    for (int jj = 0; jj < 32; jj++) {
        int idx = t + jj * 256;        // over 8192 float4 of lw2
        int j = idx >> 6;              // input-dim row (64 float4 per row)
        int n4 = (idx & 63) << 2;
        float4 v = *(const float4*)(lw2 + j * HD2 + n4);
        Bs[(n4 + 0) * LDT + j] = f2tf32(v.x);
        Bs[(n4 + 1) * LDT + j] = f2tf32(v.y);
        Bs[(n4 + 2) * LDT + j] = f2tf32(v.z);
        Bs[(n4 + 3) * LDT + j] = f2tf32(v.w);
    }
    __syncthreads();

    int warp = t >> 5, lane = t & 31;
    int warpM = warp & 1;              // 2 M-groups of 64 rows
    int warpN = warp >> 1;             // 4 N-groups of 64 cols
    int lr = lane >> 2, lc = lane & 3;

    float acc[4][8][4];
    #pragma unroll
    for (int i = 0; i < 4; i++)
        #pragma unroll
        for (int j = 0; j < 8; j++)
            #pragma unroll
            for (int c = 0; c < 4; c++) acc[i][j][c] = 0.f;

    const unsigned* Abase = As + (warpM * 64 + lr) * LDT + lc;
    const unsigned* Bbase = Bs + (warpN * 64 + lr) * LDT + lc;

    #pragma unroll
    for (int kt = 0; kt < 16; kt++) {
        int k0 = kt * 8;
        unsigned a[4][4];
        #pragma unroll
        for (int i = 0; i < 4; i++) {
            const unsigned* ap = Abase + i * 16 * LDT + k0;
            a[i][0] = ap[0]; a[i][1] = ap[8 * LDT];
            a[i][2] = ap[4]; a[i][3] = ap[8 * LDT + 4];
        }
        unsigned b[8][2];
        #pragma unroll
        for (int j = 0; j < 8; j++) {
            const unsigned* bp = Bbase + j * 8 * LDT + k0;
            b[j][0] = bp[0]; b[j][1] = bp[4];
        }
        #pragma unroll
        for (int i = 0; i < 4; i++)
            #pragma unroll
            for (int j = 0; j < 8; j++)
                mma_tf32(acc[i][j], a[i][0], a[i][1], a[i][2], a[i][3],
                         b[j][0], b[j][1]);
    }
    __syncthreads();   // all tile reads done; smem now reusable as outs

    #pragma unroll
    for (int i = 0; i < 4; i++) {
        int rloc = warpM * 64 + i * 16 + lr;
        int grow = r0 + rloc;
        #pragma unroll
        for (int j = 0; j < 8; j++) {
            int n = warpN * 64 + j * 8 + 2 * lc;
            float2 bb = *(const float2*)(b2 + n);
            float2 ag0 = make_float2(0.f, 0.f), ag1 = make_float2(0.f, 0.f);
            if (grow < NN)     ag0 = *(const float2*)(g_agg2 + grow * HD2 + n);
            if (grow + 8 < NN) ag1 = *(const float2*)(g_agg2 + (grow + 8) * HD2 + n);
            outs[rloc * LDO + n]           = acc[i][j][0] + bb.x + ag0.x;
            outs[rloc * LDO + n + 1]       = acc[i][j][1] + bb.y + ag0.y;
            outs[(rloc + 8) * LDO + n]     = acc[i][j][2] + bb.x + ag1.x;
            outs[(rloc + 8) * LDO + n + 1] = acc[i][j][3] + bb.y + ag1.y;
        }
    }
    __syncthreads();

    for (int i = t; i < 128 * HD; i += 256) {
        int r = i >> 7, c = i & 127;
        int row = r0 + r;
        if (row < NN) {
            float mu = outs[r * LDO + c];
            float hv = outs[r * LDO + c + HD];
            float sp = fmaxf(hv, 0.f) + log1pf(expf(-fabsf(hv)));
            float zz = mu + sqrtf(sp + 1e-8f) * eps[row * HD + c];
            g_z[row * HD + c] = zz;
            g_zt[row * HD + c] = f2tf32(zz);
        }
    }
}

// ---------------- hr (tf32) = z[head] * w_rel[rel] ---------------------------
__global__ __launch_bounds__(128) void hr_kernel(
    const int* __restrict__ head_ids, const int* __restrict__ rel_ids,
    const float* __restrict__ w_rel)
{
    int b = blockIdx.x;
    int k = threadIdx.x;
    float v = g_z[head_ids[b] * HD + k] * w_rel[rel_ids[b] * HD + k];
    g_hrt[b * HD + k] = f2tf32(v);
}

// ======== decoder GEMM: one 128x128 tile per CTA, 512 threads ================
// scores[m][n] = sum_k hr[m][k]*z[n][k].  Operands pre-converted to tf32.
// 16 warps laid out 4(M)x4(N), warp tile 32x32 (2 x 4 m16n8k8 subtiles).
__global__ __launch_bounds__(512) void decoder_mma(float* __restrict__ C) {
    extern __shared__ unsigned smem[];
    unsigned* As = smem;               // [128][LDT]  hr tile [m][k]
    unsigned* Bs = smem + 128 * LDT;   // [128][LDT]  z  tile [n][k]
    int n0 = blockIdx.x * 128;
    int m0 = blockIdx.y * 128;
    int t = threadIdx.x;

    // stage both tiles via cp.async (8 x uint4 per thread each)
    #pragma unroll
    for (int jj = 0; jj < 8; jj++) {
        int idx = t + jj * 512;
        int m = idx >> 5;
        int k4 = (idx & 31) << 2;
        cp_async16(As + m * LDT + k4, g_hrt + (m0 + m) * HD + k4);
    }
    #pragma unroll
    for (int jj = 0; jj < 8; jj++) {
        int idx = t + jj * 512;
        int n = idx >> 5;
        int k4 = (idx & 31) << 2;
        cp_async16_zfill(Bs + n * LDT + k4, g_zt + (n0 + n) * HD + k4,
                         (n0 + n) < NN);
    }
    asm volatile("cp.async.commit_group;");
    asm volatile("cp.async.wait_group 0;");
    __syncthreads();

    int warp = t >> 5, lane = t & 31;
    int warpM = warp >> 2;             // 0..3  -> m offset warpM*32
    int warpN = warp & 3;              // 0..3  -> n offset warpN*32
    int lr = lane >> 2, lc = lane & 3;

    float acc[2][4][4];
    #pragma unroll
    for (int i = 0; i < 2; i++)
        #pragma unroll
        for (int j = 0; j < 4; j++)
            #pragma unroll
            for (int c = 0; c < 4; c++) acc[i][j][c] = 0.f;

    const unsigned* Abase = As + (warpM * 32 + lr) * LDT + lc;
    const unsigned* Bbase = Bs + (warpN * 32 + lr) * LDT + lc;

    #pragma unroll
    for (int kt = 0; kt < 16; kt++) {
        int k0 = kt * 8;
        unsigned a[2][4];
        #pragma unroll
        for (int i = 0; i < 2; i++) {
            const unsigned* ap = Abase + i * 16 * LDT + k0;
            a[i][0] = ap[0]; a[i][1] = ap[8 * LDT];
            a[i][2] = ap[4]; a[i][3] = ap[8 * LDT + 4];
        }
        unsigned b[4][2];
        #pragma unroll
        for (int j = 0; j < 4; j++) {
            const unsigned* bp = Bbase + j * 8 * LDT + k0;
            b[j][0] = bp[0]; b[j][1] = bp[4];
        }
        #pragma unroll
        for (int i = 0; i < 2; i++)
            #pragma unroll
            for (int j = 0; j < 4; j++)
                mma_tf32(acc[i][j], a[i][0], a[i][1], a[i][2], a[i][3],
                         b[j][0], b[j][1]);
    }

    #pragma unroll
    for (int i = 0; i < 2; i++) {
        int mrow = m0 + warpM * 32 + i * 16 + lr;
        #pragma unroll
        for (int j = 0; j < 4; j++) {
            int n = n0 + warpN * 32 + j * 8 + 2 * lc;
            if (n < NN) {
                float2 v0 = make_float2(acc[i][j][0], acc[i][j][1]);
                float2 v1 = make_float2(acc[i][j][2], acc[i][j][3]);
                *(float2*)(C + (long)mrow * NN + n) = v0;
                *(float2*)(C + (long)(mrow + 8) * NN + n) = v1;
            }
        }
    }
}

// ---------------- launch ------------------------------------------------------
extern "C" void kernel_launch(void* const* d_in, const int* in_sizes, int n_in,
                              void* d_out, int out_size) {
    const int*   h        = (const int*)d_in[0];
    const int*   src      = (const int*)d_in[1];
    const int*   dst      = (const int*)d_in[2];
    const int*   etypes   = (const int*)d_in[3];
    const float* norm     = (const float*)d_in[4];
    const int*   head_ids = (const int*)d_in[5];
    const int*   rel_ids  = (const int*)d_in[6];
    const float* embed    = (const float*)d_in[7];
    const float* W1       = (const float*)d_in[8];
    const float* lw1      = (const float*)d_in[9];
    const float* b1       = (const float*)d_in[10];
    const float* W2       = (const float*)d_in[11];
    const float* lw2      = (const float*)d_in[12];
    const float* b2       = (const float*)d_in[13];
    const float* w_rel    = (const float*)d_in[14];
    const float* eps      = (const float*)d_in[15];
    float* out = (float*)d_out;

    static int smem_set = 0;
    int smem_sl1 = 2 * 128 * LDT * sizeof(unsigned);            // 135168
    int smem_sl2 = (128 + 256) * LDT * sizeof(unsigned);        // 202752
    int smem_dec = 2 * 128 * LDT * sizeof(unsigned);            // 135168
    if (!smem_set) {
        cudaFuncSetAttribute(selfloop1_mma,
                             cudaFuncAttributeMaxDynamicSharedMemorySize, smem_sl1);
        cudaFuncSetAttribute(selfloop2_mma,
                             cudaFuncAttributeMaxDynamicSharedMemorySize, smem_sl2);
        cudaFuncSetAttribute(decoder_mma,
                             cudaFuncAttributeMaxDynamicSharedMemorySize, smem_dec);
        smem_set = 1;
    }

    zero_kernel<<<(NN * HD2 / 4 + 255) / 256, 256>>>();
    gather_kernel<<<(NN * HD + 255) / 256, 256>>>(h, embed);
    edge1_kernel<<<EE / 4, 128>>>(src, dst, etypes, norm, W1);
    selfloop1_mma<<<(NN + 127) / 128, 256, smem_sl1>>>(lw1, b1);
    edge2_kernel<<<EE / 4, 128>>>(src, dst, etypes, norm, W2);
    selfloop2_mma<<<(NN + 127) / 128, 256, smem_sl2>>>(lw2, b2, eps);
    hr_kernel<<<BQ, 128>>>(head_ids, rel_ids, w_rel);

    dim3 grid((NN + 127) / 128, BQ / 128);   // (157, 16)
    decoder_mma<<<grid, 512, smem_dec>>>(out);
}